// round 12
// baseline (speedup 1.0000x reference)
#include <cuda_runtime.h>
#include <math.h>

#define Bn 512
#define Jn 101
#define Mn 50
#define En 128
#define Dn 60
#define DP 64
#define Pn 5120
#define TPB 768
#define NW  (TPB/32)
#define GRID 148

typedef unsigned long long u64;

__device__ __forceinline__ void ffma2(u64& d, u64 a, u64 b) {
    asm("fma.rn.f32x2 %0, %1, %2, %0;" : "+l"(d) : "l"(a), "l"(b));
}
__device__ __forceinline__ u64 pack2(float lo, float hi) {
    u64 r; asm("mov.b64 %0, {%1,%2};" : "=l"(r) : "f"(lo), "f"(hi)); return r;
}
__device__ __forceinline__ float psum(u64 v) {
    float lo, hi; asm("mov.b64 {%0,%1}, %2;" : "=f"(lo), "=f"(hi) : "l"(v));
    return lo + hi;
}

// ---------------- device scratch ----------------
__device__ float g_Wf2[64 * 256];  // pair-interleaved: [(k2)*256 + e*2 + parity] = Wft[2k2+par][e]
__device__ float g_bf[En];         // R_w @ Bc_b + R_b
__device__ float g_mask[Bn * Mn];  // 0 or -inf

__global__ void k_prep(const float* __restrict__ Bc_w, const float* __restrict__ Bc_b,
                       const float* __restrict__ R_w, const float* __restrict__ R_b)
{
    int e = blockIdx.x;
    int k = threadIdx.x;
    float acc = 0.f;
    for (int j = 0; j < En; j++)
        acc += R_w[e * En + j] * Bc_w[j * En + k];
    g_Wf2[(k >> 1) * 256 + e * 2 + (k & 1)] = acc;
    if (k == 0) {
        float s = R_b[e];
        for (int j = 0; j < En; j++) s += R_w[e * En + j] * Bc_b[j];
        g_bf[e] = s;
    }
}

__global__ void k_mask_init()
{
    int i = blockIdx.x * blockDim.x + threadIdx.x;
    if (i < Bn * Mn) g_mask[i] = 0.f;
}

__global__ void k_mask_scatter(const int* __restrict__ pad)
{
    int i = blockIdx.x * blockDim.x + threadIdx.x;
    if (i < Pn) {
        int b = pad[i];
        int m = pad[Pn + i];
        if (b >= 0 && b < Bn && m >= 0 && m < Mn)
            g_mask[b * Mn + m] = -INFINITY;
    }
}

// ---------------- smem layout (float offsets; 16B-aligned blocks) ----------------
#define OFF_TV    0        // 101*128 = 12928 (overlaid by per-warp (a,a) attn scratch in phase 3)
#define OFF_SU    12928    // 6400
#define OFF_TPN   19328    // 101*64 = 6464
#define OFF_CU    25792    // 6400
#define OFF_BFV   32192    // 128
#define OFF_ATW2  32320    // 64 k2 * 64 d * 2 = 8192   pair-interleaved At_w^T
#define OFF_ACW2  40512    // 8192
#define OFF_CPT2  48704    // 30 d2 * 50 m * 2 = 3000   pair-interleaved normalized cp
#define OFF_ATB   51704    // 64
#define OFF_ACB   51768    // 64
#define OFF_MSK   51832    // 64
#define OFF_IDS   51896    // ints: cids 50 + jids 101
#define SMEM_FLOATS (OFF_IDS + 152)
#define SMEM_BYTES  (SMEM_FLOATS * 4)

__device__ __forceinline__ float wredsum(float v) {
    #pragma unroll
    for (int o = 16; o > 0; o >>= 1) v += __shfl_xor_sync(0xffffffffu, v, o);
    return v;
}
__device__ __forceinline__ float wredmax(float v) {
    #pragma unroll
    for (int o = 16; o > 0; o >>= 1) v = fmaxf(v, __shfl_xor_sync(0xffffffffu, v, o));
    return v;
}

__global__ __launch_bounds__(TPB, 1) void k_main(
    const int* __restrict__ titems, const int* __restrict__ citems,
    const float* __restrict__ t_emb, const float* __restrict__ c_emb,
    const float* __restrict__ Ac_w, const float* __restrict__ Ac_b,
    const float* __restrict__ At_w, const float* __restrict__ At_b,
    float* __restrict__ out)
{
    extern __shared__ float sm[];
    float* tv    = sm + OFF_TV;
    float* su    = sm + OFF_SU;
    float* tpn   = sm + OFF_TPN;
    float* cu    = sm + OFF_CU;
    float* bfv   = sm + OFF_BFV;
    float* atw2  = sm + OFF_ATW2;
    float* acw2  = sm + OFF_ACW2;
    u64*   cpt2  = (u64*)(sm + OFF_CPT2);   // [d2*Mn + m]
    float* atb   = sm + OFF_ATB;
    float* acb   = sm + OFF_ACB;
    float* mskf  = sm + OFF_MSK;
    int*   cids  = (int*)(sm + OFF_IDS);
    int*   jids  = cids + Mn;

    const int tid = threadIdx.x;
    const int w   = tid >> 5, l = tid & 31;

    // ======== stage weights ONCE per CTA (pair-interleaved along k) ========
    if (tid < DP) {
        atb[tid] = (tid < Dn) ? At_b[tid] : 0.f;
        acb[tid] = (tid < Dn) ? Ac_b[tid] : 0.f;
    }
    if (tid < En) bfv[tid] = g_bf[tid];
    for (int i = tid; i < Dn * En; i += TPB) {
        int d = i >> 7, k = i & 127;
        int idx = (k >> 1) * 128 + d * 2 + (k & 1);
        atw2[idx] = At_w[i];
        acw2[idx] = Ac_w[i];
    }
    for (int i = tid; i < 64 * 8; i += TPB) {   // zero-pad d = 60..63
        int k2 = i >> 3, r = i & 7;
        int idx = k2 * 128 + (60 + (r >> 1)) * 2 + (r & 1);
        atw2[idx] = 0.f;
        acw2[idx] = 0.f;
    }

    // ======== persistent batch loop ========
    for (int b = blockIdx.x; b < Bn; b += GRID) {
        __syncthreads();

        if (tid < Mn) { cids[tid] = citems[b * Mn + tid]; mskf[tid] = g_mask[b * Mn + tid]; }
        if (tid < Jn) jids[tid] = titems[b * Jn + tid];
        __syncthreads();

        // gather embeddings (float4)
        {
            const float4* cef = (const float4*)c_emb;
            const float4* tef = (const float4*)t_emb;
            float4* suf = (float4*)su;
            float4* tvf = (float4*)tv;
            for (int i = tid; i < Mn * 32; i += TPB)
                suf[i] = cef[(size_t)cids[i >> 5] * 32 + (i & 31)];
            for (int i = tid; i < Jn * 32; i += TPB)
                tvf[i] = tef[(size_t)jids[i >> 5] * 32 + (i & 31)];
        }
        __syncthreads();

        // ========== phase 2: 28 items (8 heavy cu + 7 cp + 13 tp), 16B broadcasts ==========
        for (int p = w; p < 28; p += NW) {
            if (p < 8) {
                // cu pass: 13 m-rows x 2 e-cols, k4-vectorized activations, Wf2 from L2
                int g  = p & 1, q = p >> 1;       // e-half, m-block
                int e0 = g * 32 + l;              // cols e0, e0+64
                int m0 = q * 13; if (m0 > Mn - 13) m0 = Mn - 13;
                u64 accA[13], accB[13];
                #pragma unroll
                for (int r = 0; r < 13; r++) { accA[r] = 0; accB[r] = 0; }
                const u64* wp = (const u64*)g_Wf2;                    // [k2*128 + e]
                const ulonglong2* sb = (const ulonglong2*)(su + m0 * En);  // 32 per row
                #pragma unroll 2
                for (int k4 = 0; k4 < 32; k4++) {
                    u64 wA0 = wp[(2*k4  ) * 128 + e0], wB0 = wp[(2*k4  ) * 128 + e0 + 64];
                    u64 wA1 = wp[(2*k4+1) * 128 + e0], wB1 = wp[(2*k4+1) * 128 + e0 + 64];
                    #pragma unroll
                    for (int r = 0; r < 13; r++) {
                        ulonglong2 s = sb[r * 32 + k4];
                        ffma2(accA[r], s.x, wA0); ffma2(accB[r], s.x, wB0);
                        ffma2(accA[r], s.y, wA1); ffma2(accB[r], s.y, wB1);
                    }
                }
                #pragma unroll
                for (int r = 0; r < 13; r++) {
                    cu[(m0 + r) * En + e0]      = psum(accA[r]);
                    cu[(m0 + r) * En + e0 + 64] = psum(accB[r]);
                }
            } else {
                // projection pass: 8 rows x (d0=l, d1=l+32), k4-vectorized activations
                const bool iscp = (p < 15);       // 8..14 cp (7x8=56>=50), 15..27 tp (13x8=104>=101)
                const int base = iscp ? 8 * (p - 8) : 8 * (p - 15);
                const int rmax = iscp ? (Mn - 1) : (Jn - 1);
                const float* src = iscp ? su : tv;
                const u64*  wkd  = (const u64*)(iscp ? acw2 : atw2);   // [k2*64 + d]
                const float* bias = iscp ? acb : atb;
                int rows[8];
                const ulonglong2* sp[8];
                #pragma unroll
                for (int i = 0; i < 8; i++) {
                    rows[i] = min(base + i, rmax);
                    sp[i] = (const ulonglong2*)(src + rows[i] * En);
                }
                u64 a0[8], a1[8];
                #pragma unroll
                for (int i = 0; i < 8; i++) { a0[i] = 0; a1[i] = 0; }
                #pragma unroll 2
                for (int k4 = 0; k4 < 32; k4++) {
                    u64 w00 = wkd[(2*k4  ) * 64 + l];
                    u64 w01 = wkd[(2*k4  ) * 64 + l + 32];
                    u64 w10 = wkd[(2*k4+1) * 64 + l];
                    u64 w11 = wkd[(2*k4+1) * 64 + l + 32];
                    #pragma unroll
                    for (int i = 0; i < 8; i++) {
                        ulonglong2 v = sp[i][k4];
                        ffma2(a0[i], v.x, w00); ffma2(a1[i], v.x, w01);
                        ffma2(a0[i], v.y, w10); ffma2(a1[i], v.y, w11);
                    }
                }
                float bl0 = bias[l], bl1 = bias[l + 32];
                #pragma unroll
                for (int i = 0; i < 8; i++) {
                    float t0 = psum(a0[i]) + bl0;        // d = l
                    float t1 = psum(a1[i]) + bl1;        // d = l+32 (0 beyond 59)
                    float sq  = wredsum(t0 * t0 + t1 * t1);
                    float inv = 1.f / fmaxf(sqrtf(sq), 1e-6f);
                    float q0 = t0 * inv, q1 = t1 * inv;
                    if (iscp) {
                        float qo0 = __shfl_down_sync(0xffffffffu, q0, 1);
                        float qo1 = __shfl_down_sync(0xffffffffu, q1, 1);
                        if ((l & 1) == 0) {
                            cpt2[(l >> 1) * Mn + rows[i]] = pack2(q0, qo0);
                            if (l < 28)
                                cpt2[(16 + (l >> 1)) * Mn + rows[i]] = pack2(q1, qo1);
                        }
                    } else {
                        tpn[rows[i] * DP + l]      = q0;
                        tpn[rows[i] * DP + l + 32] = q1;
                    }
                }
            }
        }
        __syncthreads();

        // ========== phase 3: scores + softmax + epilogue, 5 j per warp-tile (21 tiles) ==========
        if (w < 21) {
            u64* wat = (u64*)tv + w * 250;   // per-warp (a,a)-packed attn, 5*50 u64
            const u64* cuU = (const u64*)cu;
            int j0 = 5 * w;
            int jj[5];
            const u64* tpU[5];
            #pragma unroll
            for (int i = 0; i < 5; i++) {
                jj[i] = min(j0 + i, Jn - 1);
                tpU[i] = (const u64*)(tpn + jj[i] * DP);
            }
            const bool act = (l < 25);
            const int m0 = act ? l : 0;
            const int m1 = m0 + 25;

            u64 s0[5], s1[5];
            #pragma unroll
            for (int i = 0; i < 5; i++) { s0[i] = 0; s1[i] = 0; }
            #pragma unroll 5
            for (int d2 = 0; d2 < 30; d2++) {
                u64 c0 = cpt2[d2 * Mn + m0];
                u64 c1 = cpt2[d2 * Mn + m1];
                #pragma unroll
                for (int i = 0; i < 5; i++) {
                    u64 tpv = tpU[i][d2];
                    ffma2(s0[i], tpv, c0);
                    ffma2(s1[i], tpv, c1);
                }
            }
            float mk0 = act ? mskf[m0] : -INFINITY;
            float mk1 = act ? mskf[m1] : -INFINITY;
            #pragma unroll
            for (int i = 0; i < 5; i++) {
                float v0 = psum(s0[i]) + mk0;
                float v1 = psum(s1[i]) + mk1;
                float mx = wredmax(fmaxf(v0, v1));
                float e0 = __expf(v0 - mx);
                float e1 = __expf(v1 - mx);
                float ss = wredsum(e0 + e1);
                float inv = 1.f / ss;
                if (act) {
                    float a0 = e0 * inv, a1 = e1 * inv;
                    wat[i * Mn + m0] = pack2(a0, a0);   // pre-duplicated for f32x2 broadcast
                    wat[i * Mn + m1] = pack2(a1, a1);
                }
            }
            __syncwarp();

            // epilogue: out[j] = attn[j] @ cu + bf, e-pair packed, 5 j share each cu load
            const u64* bfU = (const u64*)bfv;
            u64 o01[5], o23[5];
            #pragma unroll
            for (int i = 0; i < 5; i++) { o01[i] = bfU[2 * l]; o23[i] = bfU[2 * l + 1]; }
            #pragma unroll 5
            for (int m = 0; m < Mn; m++) {
                u64 c01 = cuU[m * 64 + 2 * l];
                u64 c23 = cuU[m * 64 + 2 * l + 1];
                #pragma unroll
                for (int i = 0; i < 5; i++) {
                    u64 aa = wat[i * Mn + m];
                    ffma2(o01[i], aa, c01);
                    ffma2(o23[i], aa, c23);
                }
            }
            u64* op = (u64*)(out + (size_t)b * Jn * En);
            #pragma unroll
            for (int i = 0; i < 5; i++) {
                op[jj[i] * 64 + 2 * l]     = o01[i];
                op[jj[i] * 64 + 2 * l + 1] = o23[i];
            }
        }
    }
}

// ---------------- launch ----------------
extern "C" void kernel_launch(void* const* d_in, const int* in_sizes, int n_in,
                              void* d_out, int out_size)
{
    const int*   titems = (const int*)d_in[0];
    const int*   citems = (const int*)d_in[1];
    const int*   pad    = (const int*)d_in[2];
    const float* t_emb  = (const float*)d_in[3];
    const float* c_emb  = (const float*)d_in[4];
    const float* Ac_w   = (const float*)d_in[5];
    const float* Ac_b   = (const float*)d_in[6];
    const float* At_w   = (const float*)d_in[7];
    const float* At_b   = (const float*)d_in[8];
    const float* Bc_w   = (const float*)d_in[9];
    const float* Bc_b   = (const float*)d_in[10];
    const float* R_w    = (const float*)d_in[11];
    const float* R_b    = (const float*)d_in[12];
    float* out = (float*)d_out;

    cudaFuncSetAttribute(k_main, cudaFuncAttributeMaxDynamicSharedMemorySize, SMEM_BYTES);

    k_prep<<<En, En>>>(Bc_w, Bc_b, R_w, R_b);
    k_mask_init<<<(Bn * Mn + 255) / 256, 256>>>();
    k_mask_scatter<<<(Pn + 255) / 256, 256>>>(pad);
    k_main<<<GRID, TPB, SMEM_BYTES>>>(titems, citems, t_emb, c_emb,
                                      Ac_w, Ac_b, At_w, At_b, out);
}

// round 13
// speedup vs baseline: 1.1528x; 1.1528x over previous
#include <cuda_runtime.h>
#include <math.h>

#define Bn 512
#define Jn 101
#define Mn 50
#define En 128
#define Dn 60
#define DP 64
#define Pn 5120
#define TPB 768
#define NW  (TPB/32)
#define GRID 148

typedef unsigned long long u64;

__device__ __forceinline__ void ffma2(u64& d, u64 a, u64 b) {
    asm("fma.rn.f32x2 %0, %1, %2, %0;" : "+l"(d) : "l"(a), "l"(b));
}
__device__ __forceinline__ u64 pack2(float lo, float hi) {
    u64 r; asm("mov.b64 %0, {%1,%2};" : "=l"(r) : "f"(lo), "f"(hi)); return r;
}
__device__ __forceinline__ float psum(u64 v) {
    float lo, hi; asm("mov.b64 {%0,%1}, %2;" : "=f"(lo), "=f"(hi) : "l"(v));
    return lo + hi;
}

// ---------------- device scratch ----------------
__device__ float g_Wf2[64 * 256];  // pair-interleaved: [(k2)*256 + e*2 + parity] = Wft[2k2+par][e]
__device__ float g_bf[En];         // R_w @ Bc_b + R_b
__device__ float g_mask[Bn * Mn];  // 0 or -inf

__global__ void k_prep(const float* __restrict__ Bc_w, const float* __restrict__ Bc_b,
                       const float* __restrict__ R_w, const float* __restrict__ R_b)
{
    int e = blockIdx.x;
    int k = threadIdx.x;
    float acc = 0.f;
    for (int j = 0; j < En; j++)
        acc += R_w[e * En + j] * Bc_w[j * En + k];
    g_Wf2[(k >> 1) * 256 + e * 2 + (k & 1)] = acc;
    if (k == 0) {
        float s = R_b[e];
        for (int j = 0; j < En; j++) s += R_w[e * En + j] * Bc_b[j];
        g_bf[e] = s;
    }
}

__global__ void k_mask_init()
{
    int i = blockIdx.x * blockDim.x + threadIdx.x;
    if (i < Bn * Mn) g_mask[i] = 0.f;
}

__global__ void k_mask_scatter(const int* __restrict__ pad)
{
    int i = blockIdx.x * blockDim.x + threadIdx.x;
    if (i < Pn) {
        int b = pad[i];
        int m = pad[Pn + i];
        if (b >= 0 && b < Bn && m >= 0 && m < Mn)
            g_mask[b * Mn + m] = -INFINITY;
    }
}

// ---------------- smem layout (float offsets; 16B-aligned blocks) ----------------
#define OFF_TV    0        // 101*128 = 12928 (overlaid by per-warp (a,a) attn scratch in phase 3)
#define OFF_SU    12928    // 6400
#define OFF_TPN   19328    // 101*64 = 6464
#define OFF_CU    25792    // 6400
#define OFF_BFV   32192    // 128
#define OFF_ATW2  32320    // 64 k2 * 64 d * 2 = 8192   pair-interleaved At_w^T
#define OFF_ACW2  40512    // 8192
#define OFF_CPT2  48704    // 30 d2 * 50 m * 2 = 3000   pair-interleaved normalized cp
#define OFF_ATB   51704    // 64
#define OFF_ACB   51768    // 64
#define OFF_MSK   51832    // 64
#define OFF_IDS   51896    // ints: cids 50 + jids 101
#define SMEM_FLOATS (OFF_IDS + 152)
#define SMEM_BYTES  (SMEM_FLOATS * 4)

__device__ __forceinline__ float wredsum(float v) {
    #pragma unroll
    for (int o = 16; o > 0; o >>= 1) v += __shfl_xor_sync(0xffffffffu, v, o);
    return v;
}
__device__ __forceinline__ float wredmax(float v) {
    #pragma unroll
    for (int o = 16; o > 0; o >>= 1) v = fmaxf(v, __shfl_xor_sync(0xffffffffu, v, o));
    return v;
}

__global__ __launch_bounds__(TPB, 1) void k_main(
    const int* __restrict__ titems, const int* __restrict__ citems,
    const float* __restrict__ t_emb, const float* __restrict__ c_emb,
    const float* __restrict__ Ac_w, const float* __restrict__ Ac_b,
    const float* __restrict__ At_w, const float* __restrict__ At_b,
    float* __restrict__ out)
{
    extern __shared__ float sm[];
    float* tv    = sm + OFF_TV;
    float* su    = sm + OFF_SU;
    float* tpn   = sm + OFF_TPN;
    float* cu    = sm + OFF_CU;
    float* bfv   = sm + OFF_BFV;
    float* atw2  = sm + OFF_ATW2;
    float* acw2  = sm + OFF_ACW2;
    u64*   cpt2  = (u64*)(sm + OFF_CPT2);   // [d2*Mn + m]
    float* atb   = sm + OFF_ATB;
    float* acb   = sm + OFF_ACB;
    float* mskf  = sm + OFF_MSK;
    int*   cids  = (int*)(sm + OFF_IDS);
    int*   jids  = cids + Mn;

    const int tid = threadIdx.x;
    const int w   = tid >> 5, l = tid & 31;

    // ======== stage weights ONCE per CTA (pair-interleaved along k) ========
    if (tid < DP) {
        atb[tid] = (tid < Dn) ? At_b[tid] : 0.f;
        acb[tid] = (tid < Dn) ? Ac_b[tid] : 0.f;
    }
    if (tid < En) bfv[tid] = g_bf[tid];
    for (int i = tid; i < Dn * En; i += TPB) {
        int d = i >> 7, k = i & 127;
        int idx = (k >> 1) * 128 + d * 2 + (k & 1);
        atw2[idx] = At_w[i];
        acw2[idx] = Ac_w[i];
    }
    for (int i = tid; i < 64 * 8; i += TPB) {   // zero-pad d = 60..63
        int k2 = i >> 3, r = i & 7;
        int idx = k2 * 128 + (60 + (r >> 1)) * 2 + (r & 1);
        atw2[idx] = 0.f;
        acw2[idx] = 0.f;
    }

    // ======== persistent batch loop ========
    for (int b = blockIdx.x; b < Bn; b += GRID) {
        __syncthreads();

        if (tid < Mn) { cids[tid] = citems[b * Mn + tid]; mskf[tid] = g_mask[b * Mn + tid]; }
        if (tid < Jn) jids[tid] = titems[b * Jn + tid];
        __syncthreads();

        // gather embeddings (float4)
        {
            const float4* cef = (const float4*)c_emb;
            const float4* tef = (const float4*)t_emb;
            float4* suf = (float4*)su;
            float4* tvf = (float4*)tv;
            for (int i = tid; i < Mn * 32; i += TPB)
                suf[i] = cef[(size_t)cids[i >> 5] * 32 + (i & 31)];
            for (int i = tid; i < Jn * 32; i += TPB)
                tvf[i] = tef[(size_t)jids[i >> 5] * 32 + (i & 31)];
        }
        __syncthreads();

        // ========== phase 2: 47 items (16 cu + 10 cp + 21 tp), two balanced rounds ==========
        for (int p = w; p < 47; p += NW) {
            if (p < 16) {
                // cu pass: 13 m-rows x 1 e-col, 16B activation broadcasts, Wf2 from L2
                int t  = p;                       // 0..15
                int e0 = (t & 3) * 32 + l;
                int m0 = (t >> 2) * 13; if (m0 > Mn - 13) m0 = Mn - 13;
                u64 acc[13];
                #pragma unroll
                for (int r = 0; r < 13; r++) acc[r] = 0;
                const u64* wp = (const u64*)g_Wf2;                        // [k2*128 + e]
                const ulonglong2* sb = (const ulonglong2*)(su + m0 * En); // 32 per row
                #pragma unroll 2
                for (int k4 = 0; k4 < 32; k4++) {
                    u64 wv0 = wp[(2*k4    ) * 128 + e0];
                    u64 wv1 = wp[(2*k4 + 1) * 128 + e0];
                    #pragma unroll
                    for (int r = 0; r < 13; r++) {
                        ulonglong2 s = sb[r * 32 + k4];
                        ffma2(acc[r], s.x, wv0);
                        ffma2(acc[r], s.y, wv1);
                    }
                }
                #pragma unroll
                for (int r = 0; r < 13; r++)
                    cu[(m0 + r) * En + e0] = psum(acc[r]);
            } else {
                // projection pass: 5 rows x (d0=l, d1=l+32), 16B activation broadcasts
                const bool iscp = (p < 26);       // 16..25 cp (10x5=50), 26..46 tp (21x5>=101)
                const int base = iscp ? 5 * (p - 16) : 5 * (p - 26);
                const int rmax = iscp ? (Mn - 1) : (Jn - 1);
                const float* src = iscp ? su : tv;
                const u64*  wkd  = (const u64*)(iscp ? acw2 : atw2);   // [k2*64 + d]
                const float* bias = iscp ? acb : atb;
                int rows[5];
                const ulonglong2* sp[5];
                #pragma unroll
                for (int i = 0; i < 5; i++) {
                    rows[i] = min(base + i, rmax);
                    sp[i] = (const ulonglong2*)(src + rows[i] * En);
                }
                u64 a0[5], a1[5];
                #pragma unroll
                for (int i = 0; i < 5; i++) { a0[i] = 0; a1[i] = 0; }
                #pragma unroll 2
                for (int k4 = 0; k4 < 32; k4++) {
                    u64 w00 = wkd[(2*k4    ) * 64 + l];
                    u64 w01 = wkd[(2*k4    ) * 64 + l + 32];
                    u64 w10 = wkd[(2*k4 + 1) * 64 + l];
                    u64 w11 = wkd[(2*k4 + 1) * 64 + l + 32];
                    #pragma unroll
                    for (int i = 0; i < 5; i++) {
                        ulonglong2 v = sp[i][k4];
                        ffma2(a0[i], v.x, w00); ffma2(a1[i], v.x, w01);
                        ffma2(a0[i], v.y, w10); ffma2(a1[i], v.y, w11);
                    }
                }
                float bl0 = bias[l], bl1 = bias[l + 32];
                #pragma unroll
                for (int i = 0; i < 5; i++) {
                    float t0 = psum(a0[i]) + bl0;        // d = l
                    float t1 = psum(a1[i]) + bl1;        // d = l+32 (0 beyond 59)
                    float sq  = wredsum(t0 * t0 + t1 * t1);
                    float inv = 1.f / fmaxf(sqrtf(sq), 1e-6f);
                    float q0 = t0 * inv, q1 = t1 * inv;
                    if (iscp) {
                        float qo0 = __shfl_down_sync(0xffffffffu, q0, 1);
                        float qo1 = __shfl_down_sync(0xffffffffu, q1, 1);
                        if ((l & 1) == 0) {
                            cpt2[(l >> 1) * Mn + rows[i]] = pack2(q0, qo0);
                            if (l < 28)
                                cpt2[(16 + (l >> 1)) * Mn + rows[i]] = pack2(q1, qo1);
                        }
                    } else {
                        tpn[rows[i] * DP + l]      = q0;
                        tpn[rows[i] * DP + l + 32] = q1;
                    }
                }
            }
        }
        __syncthreads();

        // ========== phase 3: scores + softmax + epilogue, 5 j per warp-tile (21 tiles) ==========
        if (w < 21) {
            u64* wat = (u64*)tv + w * 250;   // per-warp (a,a)-packed attn, 5*50 u64
            const u64* cuU = (const u64*)cu;
            int j0 = 5 * w;
            int jj[5];
            const ulonglong2* tpV[5];
            #pragma unroll
            for (int i = 0; i < 5; i++) {
                jj[i] = min(j0 + i, Jn - 1);
                tpV[i] = (const ulonglong2*)(tpn + jj[i] * DP);
            }
            const bool act = (l < 25);
            const int m0 = act ? l : 0;
            const int m1 = m0 + 25;

            u64 s0[5], s1[5];
            #pragma unroll
            for (int i = 0; i < 5; i++) { s0[i] = 0; s1[i] = 0; }
            #pragma unroll 3
            for (int d4 = 0; d4 < 15; d4++) {
                u64 c00 = cpt2[(2*d4    ) * Mn + m0];
                u64 c01 = cpt2[(2*d4 + 1) * Mn + m0];
                u64 c10 = cpt2[(2*d4    ) * Mn + m1];
                u64 c11 = cpt2[(2*d4 + 1) * Mn + m1];
                #pragma unroll
                for (int i = 0; i < 5; i++) {
                    ulonglong2 t = tpV[i][d4];
                    ffma2(s0[i], t.x, c00); ffma2(s0[i], t.y, c01);
                    ffma2(s1[i], t.x, c10); ffma2(s1[i], t.y, c11);
                }
            }
            float mk0 = act ? mskf[m0] : -INFINITY;
            float mk1 = act ? mskf[m1] : -INFINITY;
            #pragma unroll
            for (int i = 0; i < 5; i++) {
                float v0 = psum(s0[i]) + mk0;
                float v1 = psum(s1[i]) + mk1;
                float mx = wredmax(fmaxf(v0, v1));
                float e0 = __expf(v0 - mx);
                float e1 = __expf(v1 - mx);
                float ss = wredsum(e0 + e1);
                float inv = 1.f / ss;
                if (act) {
                    float a0 = e0 * inv, a1 = e1 * inv;
                    wat[i * Mn + m0] = pack2(a0, a0);   // pre-duplicated for f32x2 broadcast
                    wat[i * Mn + m1] = pack2(a1, a1);
                }
            }
            __syncwarp();

            // epilogue: out[j] = attn[j] @ cu + bf, e-pair packed, 5 j share each cu load
            const u64* bfU = (const u64*)bfv;
            u64 o01[5], o23[5];
            #pragma unroll
            for (int i = 0; i < 5; i++) { o01[i] = bfU[2 * l]; o23[i] = bfU[2 * l + 1]; }
            #pragma unroll 5
            for (int m = 0; m < Mn; m++) {
                u64 c01 = cuU[m * 64 + 2 * l];
                u64 c23 = cuU[m * 64 + 2 * l + 1];
                #pragma unroll
                for (int i = 0; i < 5; i++) {
                    u64 aa = wat[i * Mn + m];
                    ffma2(o01[i], aa, c01);
                    ffma2(o23[i], aa, c23);
                }
            }
            u64* op = (u64*)(out + (size_t)b * Jn * En);
            #pragma unroll
            for (int i = 0; i < 5; i++) {
                op[jj[i] * 64 + 2 * l]     = o01[i];
                op[jj[i] * 64 + 2 * l + 1] = o23[i];
            }
        }
    }
}

// ---------------- launch ----------------
extern "C" void kernel_launch(void* const* d_in, const int* in_sizes, int n_in,
                              void* d_out, int out_size)
{
    const int*   titems = (const int*)d_in[0];
    const int*   citems = (const int*)d_in[1];
    const int*   pad    = (const int*)d_in[2];
    const float* t_emb  = (const float*)d_in[3];
    const float* c_emb  = (const float*)d_in[4];
    const float* Ac_w   = (const float*)d_in[5];
    const float* Ac_b   = (const float*)d_in[6];
    const float* At_w   = (const float*)d_in[7];
    const float* At_b   = (const float*)d_in[8];
    const float* Bc_w   = (const float*)d_in[9];
    const float* Bc_b   = (const float*)d_in[10];
    const float* R_w    = (const float*)d_in[11];
    const float* R_b    = (const float*)d_in[12];
    float* out = (float*)d_out;

    cudaFuncSetAttribute(k_main, cudaFuncAttributeMaxDynamicSharedMemorySize, SMEM_BYTES);

    k_prep<<<En, En>>>(Bc_w, Bc_b, R_w, R_b);
    k_mask_init<<<(Bn * Mn + 255) / 256, 256>>>();
    k_mask_scatter<<<(Pn + 255) / 256, 256>>>(pad);
    k_main<<<GRID, TPB, SMEM_BYTES>>>(titems, citems, t_emb, c_emb,
                                      Ac_w, Ac_b, At_w, At_b, out);
}

// round 14
// speedup vs baseline: 1.4263x; 1.2373x over previous
#include <cuda_runtime.h>
#include <math.h>

#define Bn 512
#define Jn 101
#define Mn 50
#define En 128
#define Dn 60
#define DP 64
#define Pn 5120
#define TPB 768
#define NW  (TPB/32)
#define GRID 148
#define TVS 132          // activation row stride (≡4 mod 32: conflict-free mma A loads)
#define WS72 72          // weight row stride for mma B loads

typedef unsigned long long u64;
typedef unsigned int u32;

__device__ __forceinline__ void ffma2(u64& d, u64 a, u64 b) {
    asm("fma.rn.f32x2 %0, %1, %2, %0;" : "+l"(d) : "l"(a), "l"(b));
}
__device__ __forceinline__ u64 pack2(float lo, float hi) {
    u64 r; asm("mov.b64 %0, {%1,%2};" : "=l"(r) : "f"(lo), "f"(hi)); return r;
}
__device__ __forceinline__ float psum(u64 v) {
    float lo, hi; asm("mov.b64 {%0,%1}, %2;" : "=f"(lo), "=f"(hi) : "l"(v));
    return lo + hi;
}
__device__ __forceinline__ u32 f2tf(float f) {
    u32 r; asm("cvt.rna.tf32.f32 %0, %1;" : "=r"(r) : "f"(f)); return r;
}
__device__ __forceinline__ void mma_tf32(float* c, u32 a0, u32 a1, u32 a2, u32 a3,
                                         u32 b0, u32 b1) {
    asm("mma.sync.aligned.m16n8k8.row.col.f32.tf32.tf32.f32 "
        "{%0,%1,%2,%3}, {%4,%5,%6,%7}, {%8,%9}, {%0,%1,%2,%3};"
        : "+f"(c[0]), "+f"(c[1]), "+f"(c[2]), "+f"(c[3])
        : "r"(a0), "r"(a1), "r"(a2), "r"(a3), "r"(b0), "r"(b1));
}

// ---------------- device scratch ----------------
__device__ float g_Wf2[64 * 256];  // pair-interleaved: [(k2)*256 + e*2 + parity] = Wft[2k2+par][e]
__device__ float g_bf[En];         // R_w @ Bc_b + R_b
__device__ float g_mask[Bn * Mn];  // 0 or -inf

__global__ void k_prep(const float* __restrict__ Bc_w, const float* __restrict__ Bc_b,
                       const float* __restrict__ R_w, const float* __restrict__ R_b)
{
    int e = blockIdx.x;
    int k = threadIdx.x;
    float acc = 0.f;
    for (int j = 0; j < En; j++)
        acc += R_w[e * En + j] * Bc_w[j * En + k];
    g_Wf2[(k >> 1) * 256 + e * 2 + (k & 1)] = acc;
    if (k == 0) {
        float s = R_b[e];
        for (int j = 0; j < En; j++) s += R_w[e * En + j] * Bc_b[j];
        g_bf[e] = s;
    }
}

__global__ void k_mask_init()
{
    int i = blockIdx.x * blockDim.x + threadIdx.x;
    if (i < Bn * Mn) g_mask[i] = 0.f;
}

__global__ void k_mask_scatter(const int* __restrict__ pad)
{
    int i = blockIdx.x * blockDim.x + threadIdx.x;
    if (i < Pn) {
        int b = pad[i];
        int m = pad[Pn + i];
        if (b >= 0 && b < Bn && m >= 0 && m < Mn)
            g_mask[b * Mn + m] = -INFINITY;
    }
}

// ---------------- smem layout (float offsets) ----------------
#define OFF_TV    0        // 112 rows * 132 = 14784 (wat scratch overlay in phase 3)
#define OFF_SU    14784    // 64 rows * 132 = 8448
#define OFF_TPN   23232    // 101*64 = 6464
#define OFF_CU    29696    // 50*128 = 6400
#define OFF_ATW   36096    // 128*72 = 9216 (tf32 bits, B-layout [k][d])
#define OFF_ACW   45312    // 9216
#define OFF_CPT2  54528    // 30 d2 * 50 m * 2 = 3000
#define OFF_BFV   57528    // 128
#define OFF_ATB   57656    // 64
#define OFF_ACB   57720    // 64
#define OFF_MSK   57784    // 64
#define OFF_IDS   57848    // ints: jids 112 + cids 64
#define SMEM_FLOATS (OFF_IDS + 176)
#define SMEM_BYTES  (SMEM_FLOATS * 4)

__device__ __forceinline__ float wredsum(float v) {
    #pragma unroll
    for (int o = 16; o > 0; o >>= 1) v += __shfl_xor_sync(0xffffffffu, v, o);
    return v;
}
__device__ __forceinline__ float wredmax(float v) {
    #pragma unroll
    for (int o = 16; o > 0; o >>= 1) v = fmaxf(v, __shfl_xor_sync(0xffffffffu, v, o));
    return v;
}

__global__ __launch_bounds__(TPB, 1) void k_main(
    const int* __restrict__ titems, const int* __restrict__ citems,
    const float* __restrict__ t_emb, const float* __restrict__ c_emb,
    const float* __restrict__ Ac_w, const float* __restrict__ Ac_b,
    const float* __restrict__ At_w, const float* __restrict__ At_b,
    float* __restrict__ out)
{
    extern __shared__ float sm[];
    float* tv    = sm + OFF_TV;
    float* su    = sm + OFF_SU;
    float* tpn   = sm + OFF_TPN;
    float* cu    = sm + OFF_CU;
    u32*   atwU  = (u32*)(sm + OFF_ATW);
    u32*   acwU  = (u32*)(sm + OFF_ACW);
    u64*   cpt2  = (u64*)(sm + OFF_CPT2);   // [d2*Mn + m]
    float* bfv   = sm + OFF_BFV;
    float* atb   = sm + OFF_ATB;
    float* acb   = sm + OFF_ACB;
    float* mskf  = sm + OFF_MSK;
    int*   jids  = (int*)(sm + OFF_IDS);
    int*   cids  = jids + 112;

    const int tid = threadIdx.x;
    const int w   = tid >> 5, l = tid & 31;
    const int qg  = l >> 2;      // lane/4 (fragment row group)
    const int qt  = l & 3;       // lane%4

    // ======== stage weights ONCE per CTA (tf32 B-layout [k][d], stride 72) ========
    if (tid < DP) {
        atb[tid] = (tid < Dn) ? At_b[tid] : 0.f;
        acb[tid] = (tid < Dn) ? Ac_b[tid] : 0.f;
    }
    if (tid < En) bfv[tid] = g_bf[tid];
    for (int i = tid; i < Dn * En; i += TPB) {
        int d = i >> 7, k = i & 127;
        atwU[k * WS72 + d] = f2tf(At_w[i]);
        acwU[k * WS72 + d] = f2tf(Ac_w[i]);
    }
    for (int i = tid; i < En * 4; i += TPB) {   // zero d = 60..63
        int k = i >> 2, d = 60 + (i & 3);
        atwU[k * WS72 + d] = 0u;
        acwU[k * WS72 + d] = 0u;
    }

    // ======== persistent batch loop ========
    for (int b = blockIdx.x; b < Bn; b += GRID) {
        __syncthreads();   // previous batch fully done

        if (tid < 112) jids[tid] = titems[b * Jn + min(tid, Jn - 1)];
        if (tid >= 128 && tid < 192) cids[tid - 128] = citems[b * Mn + min(tid - 128, Mn - 1)];
        if (tid >= 192 && tid < 192 + Mn) mskf[tid - 192] = g_mask[b * Mn + (tid - 192)];
        __syncthreads();

        // gather embeddings (float4, padded stride TVS=132 -> 33 float4/row)
        {
            const float4* cef = (const float4*)c_emb;
            const float4* tef = (const float4*)t_emb;
            float4* suf = (float4*)su;
            float4* tvf = (float4*)tv;
            for (int i = tid; i < 64 * 32; i += TPB)
                suf[(i >> 5) * 33 + (i & 31)] = cef[(size_t)cids[i >> 5] * 32 + (i & 31)];
            for (int i = tid; i < 112 * 32; i += TPB)
                tvf[(i >> 5) * 33 + (i & 31)] = tef[(size_t)jids[i >> 5] * 32 + (i & 31)];
        }
        __syncthreads();

        // ========== phase 2: 21 items, single round (7 tp-mma + 4 cp-mma + 10 cu) ==========
        if (w < 11) {
            // ---- projection via tf32 mma: tile of 16 rows x 64 d ----
            const bool iscp = (w >= 7);
            const int tile  = iscp ? (w - 7) : w;
            const float* src = iscp ? su : tv;
            const u32*  wb   = iscp ? acwU : atwU;
            const float* bias = iscp ? acb : atb;
            const int rA = tile * 16 + qg;
            const int rB = rA + 8;
            const float* pA = src + rA * TVS + qt;
            const float* pB = src + rB * TVS + qt;

            float c[8][4];
            #pragma unroll
            for (int nt = 0; nt < 8; nt++)
                #pragma unroll
                for (int j = 0; j < 4; j++) c[nt][j] = 0.f;

            #pragma unroll 4
            for (int ks = 0; ks < 16; ks++) {
                u32 a0 = f2tf(pA[ks * 8]);
                u32 a2 = f2tf(pA[ks * 8 + 4]);
                u32 a1 = f2tf(pB[ks * 8]);
                u32 a3 = f2tf(pB[ks * 8 + 4]);
                const u32* wrow0 = wb + (ks * 8 + qt) * WS72 + qg;
                const u32* wrow1 = wrow0 + 4 * WS72;
                #pragma unroll
                for (int nt = 0; nt < 8; nt++) {
                    u32 b0 = wrow0[nt * 8];
                    u32 b1 = wrow1[nt * 8];
                    mma_tf32(c[nt], a0, a1, a2, a3, b0, b1);
                }
            }
            // bias, norm (quad-reduce), normalized store
            #pragma unroll
            for (int nt = 0; nt < 8; nt++) {
                int d0 = nt * 8 + 2 * qt;
                float b0f = bias[d0], b1f = bias[d0 + 1];
                c[nt][0] += b0f; c[nt][1] += b1f;
                c[nt][2] += b0f; c[nt][3] += b1f;
            }
            float sa = 0.f, sb = 0.f;
            #pragma unroll
            for (int nt = 0; nt < 8; nt++) {
                sa += c[nt][0]*c[nt][0] + c[nt][1]*c[nt][1];
                sb += c[nt][2]*c[nt][2] + c[nt][3]*c[nt][3];
            }
            sa += __shfl_xor_sync(0xffffffffu, sa, 1);
            sa += __shfl_xor_sync(0xffffffffu, sa, 2);
            sb += __shfl_xor_sync(0xffffffffu, sb, 1);
            sb += __shfl_xor_sync(0xffffffffu, sb, 2);
            float iva = 1.f / fmaxf(sqrtf(sa), 1e-6f);
            float ivb = 1.f / fmaxf(sqrtf(sb), 1e-6f);
            if (!iscp) {
                u64* tpq = (u64*)tpn;
                #pragma unroll
                for (int nt = 0; nt < 8; nt++) {
                    if (rA < Jn) tpq[rA * 32 + nt * 4 + qt] = pack2(c[nt][0]*iva, c[nt][1]*iva);
                    if (rB < Jn) tpq[rB * 32 + nt * 4 + qt] = pack2(c[nt][2]*ivb, c[nt][3]*ivb);
                }
            } else {
                #pragma unroll
                for (int nt = 0; nt < 8; nt++) {
                    int d2 = nt * 4 + qt;
                    if (d2 < 30) {
                        if (rA < Mn) cpt2[d2 * Mn + rA] = pack2(c[nt][0]*iva, c[nt][1]*iva);
                        if (rB < Mn) cpt2[d2 * Mn + rB] = pack2(c[nt][2]*ivb, c[nt][3]*ivb);
                    }
                }
            }
        } else if (w < 21) {
            // ---- cu pass: 10 m-rows x 2 e-cols, f32x2, Wf2 from L2 (R12-proven) ----
            int t  = w - 11;                 // 0..9
            int g  = t & 1, q = t >> 1;      // e-half, m-block
            int e0 = g * 32 + l;             // cols e0, e0+64
            int m0 = q * 10;
            u64 accA[10], accB[10];
            #pragma unroll
            for (int r = 0; r < 10; r++) { accA[r] = 0; accB[r] = 0; }
            const u64* wp = (const u64*)g_Wf2;                    // [k2*128 + e]
            const ulonglong2* sb2 = (const ulonglong2*)(su + m0 * TVS);  // 33 per row
            #pragma unroll 2
            for (int k4 = 0; k4 < 32; k4++) {
                u64 wA0 = wp[(2*k4  ) * 128 + e0], wB0 = wp[(2*k4  ) * 128 + e0 + 64];
                u64 wA1 = wp[(2*k4+1) * 128 + e0], wB1 = wp[(2*k4+1) * 128 + e0 + 64];
                #pragma unroll
                for (int r = 0; r < 10; r++) {
                    ulonglong2 s = sb2[r * 33 + k4];
                    ffma2(accA[r], s.x, wA0); ffma2(accB[r], s.x, wB0);
                    ffma2(accA[r], s.y, wA1); ffma2(accB[r], s.y, wB1);
                }
            }
            #pragma unroll
            for (int r = 0; r < 10; r++) {
                cu[(m0 + r) * En + e0]      = psum(accA[r]);
                cu[(m0 + r) * En + e0 + 64] = psum(accB[r]);
            }
        }
        __syncthreads();

        // ========== phase 3: scores + softmax + epilogue, 5 j per warp-tile (21 tiles) ==========
        if (w < 21) {
            u64* wat = (u64*)tv + w * 250;   // tv dead; per-warp (a,a)-packed attn
            const u64* cuU = (const u64*)cu;
            int j0 = 5 * w;
            int jj[5];
            const ulonglong2* tpV[5];
            #pragma unroll
            for (int i = 0; i < 5; i++) {
                jj[i] = min(j0 + i, Jn - 1);
                tpV[i] = (const ulonglong2*)(tpn + jj[i] * DP);
            }
            const bool act = (l < 25);
            const int m0 = act ? l : 0;
            const int m1 = m0 + 25;

            u64 s0[5], s1[5];
            #pragma unroll
            for (int i = 0; i < 5; i++) { s0[i] = 0; s1[i] = 0; }
            #pragma unroll 3
            for (int d4 = 0; d4 < 15; d4++) {
                u64 c00 = cpt2[(2*d4    ) * Mn + m0];
                u64 c01 = cpt2[(2*d4 + 1) * Mn + m0];
                u64 c10 = cpt2[(2*d4    ) * Mn + m1];
                u64 c11 = cpt2[(2*d4 + 1) * Mn + m1];
                #pragma unroll
                for (int i = 0; i < 5; i++) {
                    ulonglong2 t = tpV[i][d4];
                    ffma2(s0[i], t.x, c00); ffma2(s0[i], t.y, c01);
                    ffma2(s1[i], t.x, c10); ffma2(s1[i], t.y, c11);
                }
            }
            float mk0 = act ? mskf[m0] : -INFINITY;
            float mk1 = act ? mskf[m1] : -INFINITY;
            #pragma unroll
            for (int i = 0; i < 5; i++) {
                float v0 = psum(s0[i]) + mk0;
                float v1 = psum(s1[i]) + mk1;
                float mx = wredmax(fmaxf(v0, v1));
                float e0 = __expf(v0 - mx);
                float e1 = __expf(v1 - mx);
                float ss = wredsum(e0 + e1);
                float inv = 1.f / ss;
                if (act) {
                    float a0 = e0 * inv, a1 = e1 * inv;
                    wat[i * Mn + m0] = pack2(a0, a0);
                    wat[i * Mn + m1] = pack2(a1, a1);
                }
            }
            __syncwarp();

            const u64* bfU = (const u64*)bfv;
            u64 o01[5], o23[5];
            #pragma unroll
            for (int i = 0; i < 5; i++) { o01[i] = bfU[2 * l]; o23[i] = bfU[2 * l + 1]; }
            #pragma unroll 5
            for (int m = 0; m < Mn; m++) {
                u64 c01 = cuU[m * 64 + 2 * l];
                u64 c23 = cuU[m * 64 + 2 * l + 1];
                #pragma unroll
                for (int i = 0; i < 5; i++) {
                    u64 aa = wat[i * Mn + m];
                    ffma2(o01[i], aa, c01);
                    ffma2(o23[i], aa, c23);
                }
            }
            u64* op = (u64*)(out + (size_t)b * Jn * En);
            #pragma unroll
            for (int i = 0; i < 5; i++) {
                op[jj[i] * 64 + 2 * l]     = o01[i];
                op[jj[i] * 64 + 2 * l + 1] = o23[i];
            }
        }
    }
}

// ---------------- launch ----------------
extern "C" void kernel_launch(void* const* d_in, const int* in_sizes, int n_in,
                              void* d_out, int out_size)
{
    const int*   titems = (const int*)d_in[0];
    const int*   citems = (const int*)d_in[1];
    const int*   pad    = (const int*)d_in[2];
    const float* t_emb  = (const float*)d_in[3];
    const float* c_emb  = (const float*)d_in[4];
    const float* Ac_w   = (const float*)d_in[5];
    const float* Ac_b   = (const float*)d_in[6];
    const float* At_w   = (const float*)d_in[7];
    const float* At_b   = (const float*)d_in[8];
    const float* Bc_w   = (const float*)d_in[9];
    const float* Bc_b   = (const float*)d_in[10];
    const float* R_w    = (const float*)d_in[11];
    const float* R_b    = (const float*)d_in[12];
    float* out = (float*)d_out;

    cudaFuncSetAttribute(k_main, cudaFuncAttributeMaxDynamicSharedMemorySize, SMEM_BYTES);

    k_prep<<<En, En>>>(Bc_w, Bc_b, R_w, R_b);
    k_mask_init<<<(Bn * Mn + 255) / 256, 256>>>();
    k_mask_scatter<<<(Pn + 255) / 256, 256>>>(pad);
    k_main<<<GRID, TPB, SMEM_BYTES>>>(titems, citems, t_emb, c_emb,
                                      Ac_w, Ac_b, At_w, At_b, out);
}